// round 1
// baseline (speedup 1.0000x reference)
#include <cuda_runtime.h>
#include <cstdint>

#define Bz 2
#define Lz 1024
#define Mz (Bz*Lz)      // 2048
#define DM 768
#define DI 1536
#define DI2 3072
#define DS 16
#define RK 48
#define XDB 80

// ---------------- scratch (no cudaMalloc allowed) ----------------
__device__ __align__(16) float g_xz[Mz*DI2];     // in-proj output: x | z
__device__ __align__(16) float g_xact[Mz*DI];    // conv+silu(x)
__device__ __align__(16) float g_xdbl[Mz*XDB];   // dt_low | k | q
__device__ __align__(16) float g_dt[Mz*DI];      // dt head output
__device__ float4 g_pack[Mz*DI];                 // (W, dtt, D*x, silu(z))
__device__ __align__(16) float g_knq[Mz*48];     // k[16], k^2[16], q[16] per (b,t)
__device__ __align__(16) float g_yg[Mz*DI];      // gated scan output

// ================= fp32 GEMM: C[M,N] = A[M,K] * B[N,K]^T =================
// 128x128 tile, BK=8, 256 threads, 8x8 micro-tile.
__global__ __launch_bounds__(256, 2)
void sgemm128(const float* __restrict__ A, const float* __restrict__ B,
              float* __restrict__ C, int M, int N, int K) {
    __shared__ float As[8][132];
    __shared__ float Bs[8][132];
    int tid = threadIdx.x;
    int row0 = blockIdx.y * 128;
    int col0 = blockIdx.x * 128;
    int lr = tid >> 1;              // 0..127
    int lc = (tid & 1) * 4;         // 0 or 4
    int tx = tid & 15, ty = tid >> 4;
    float acc[8][8];
#pragma unroll
    for (int i = 0; i < 8; i++)
#pragma unroll
        for (int j = 0; j < 8; j++) acc[i][j] = 0.f;

    for (int k0 = 0; k0 < K; k0 += 8) {
        float4 av = *reinterpret_cast<const float4*>(A + (size_t)(row0 + lr) * K + k0 + lc);
        float4 bv = *reinterpret_cast<const float4*>(B + (size_t)(col0 + lr) * K + k0 + lc);
        As[lc + 0][lr] = av.x; As[lc + 1][lr] = av.y; As[lc + 2][lr] = av.z; As[lc + 3][lr] = av.w;
        Bs[lc + 0][lr] = bv.x; Bs[lc + 1][lr] = bv.y; Bs[lc + 2][lr] = bv.z; Bs[lc + 3][lr] = bv.w;
        __syncthreads();
#pragma unroll
        for (int k = 0; k < 8; k++) {
            float a8[8], b8[8];
#pragma unroll
            for (int i = 0; i < 8; i++) a8[i] = As[k][ty * 8 + i];
#pragma unroll
            for (int j = 0; j < 8; j++) b8[j] = Bs[k][tx * 8 + j];
#pragma unroll
            for (int i = 0; i < 8; i++)
#pragma unroll
                for (int j = 0; j < 8; j++)
                    acc[i][j] = fmaf(a8[i], b8[j], acc[i][j]);
        }
        __syncthreads();
    }
#pragma unroll
    for (int i = 0; i < 8; i++) {
        float* cp = C + (size_t)(row0 + ty * 8 + i) * N + col0 + tx * 8;
#pragma unroll
        for (int j = 0; j < 8; j += 4) {
            float4 v = make_float4(acc[i][j], acc[i][j + 1], acc[i][j + 2], acc[i][j + 3]);
            *reinterpret_cast<float4*>(cp + j) = v;
        }
    }
}

// ================= depthwise causal conv (k=4) + SiLU =================
// x lives in g_xz[:, 0:DI]. Output g_xact. Each thread: one (b,d), 64 timesteps.
__global__ void conv_silu_kernel(const float* __restrict__ conv_w,
                                 const float* __restrict__ conv_b) {
    int d = blockIdx.x * 128 + threadIdx.x;
    int tc = blockIdx.y;   // chunk of 64 timesteps
    int b = blockIdx.z;
    float w0 = conv_w[d * 4 + 0], w1 = conv_w[d * 4 + 1];
    float w2 = conv_w[d * 4 + 2], w3 = conv_w[d * 4 + 3];
    float bias = conv_b[d];
    int t0 = tc * 64;
    size_t base = (size_t)b * Lz;
    float xm3 = (t0 >= 3) ? g_xz[(base + t0 - 3) * DI2 + d] : 0.f;
    float xm2 = (t0 >= 2) ? g_xz[(base + t0 - 2) * DI2 + d] : 0.f;
    float xm1 = (t0 >= 1) ? g_xz[(base + t0 - 1) * DI2 + d] : 0.f;
    for (int t = t0; t < t0 + 64; t++) {
        float xc = g_xz[(base + t) * DI2 + d];
        float a = w0 * xm3 + w1 * xm2 + w2 * xm1 + w3 * xc + bias;
        float s = a / (1.f + __expf(-a));
        g_xact[(base + t) * DI + d] = s;
        xm3 = xm2; xm2 = xm1; xm1 = xc;
    }
}

// ================= x_dbl = xact(2048x1536) @ x_proj_w(80x1536)^T =================
// Block: 32 rows x 80 cols, BK=16, 256 threads, 2x5 micro.
__global__ __launch_bounds__(256)
void xdbl_kernel(const float* __restrict__ Wp) {
    __shared__ float As[16][34];
    __shared__ float Bs[16][82];
    int tid = threadIdx.x;
    int m0 = blockIdx.x * 32;
    int tx = tid & 15, ty = tid >> 4;
    int row = ty * 2, col = tx * 5;
    float acc[2][5];
#pragma unroll
    for (int i = 0; i < 2; i++)
#pragma unroll
        for (int j = 0; j < 5; j++) acc[i][j] = 0.f;

    for (int k0 = 0; k0 < DI; k0 += 16) {
        if (tid < 128) {
            int r = tid >> 2, c4 = (tid & 3) * 4;
            float4 v = *reinterpret_cast<const float4*>(g_xact + (size_t)(m0 + r) * DI + k0 + c4);
            As[c4 + 0][r] = v.x; As[c4 + 1][r] = v.y; As[c4 + 2][r] = v.z; As[c4 + 3][r] = v.w;
        }
        for (int s = tid; s < 320; s += 256) {
            int r = s >> 2, c4 = (s & 3) * 4;
            float4 v = *reinterpret_cast<const float4*>(Wp + (size_t)r * DI + k0 + c4);
            Bs[c4 + 0][r] = v.x; Bs[c4 + 1][r] = v.y; Bs[c4 + 2][r] = v.z; Bs[c4 + 3][r] = v.w;
        }
        __syncthreads();
#pragma unroll
        for (int k = 0; k < 16; k++) {
            float a0 = As[k][row], a1 = As[k][row + 1];
            float bb[5];
#pragma unroll
            for (int j = 0; j < 5; j++) bb[j] = Bs[k][col + j];
#pragma unroll
            for (int j = 0; j < 5; j++) {
                acc[0][j] = fmaf(a0, bb[j], acc[0][j]);
                acc[1][j] = fmaf(a1, bb[j], acc[1][j]);
            }
        }
        __syncthreads();
    }
#pragma unroll
    for (int i = 0; i < 2; i++)
#pragma unroll
        for (int j = 0; j < 5; j++)
            g_xdbl[(size_t)(m0 + row + i) * XDB + col + j] = acc[i][j];
}

// ================= dt = dt_low(2048x48) @ dt_head_w(1536x48)^T =================
// Block 64 rows x 128 cols, K=48 single tile, 4x8 micro.
__global__ __launch_bounds__(256)
void dt_kernel(const float* __restrict__ Wd) {
    __shared__ float As[48][66];
    __shared__ float Bs[48][130];
    int tid = threadIdx.x;
    int n0 = blockIdx.x * 128;
    int m0 = blockIdx.y * 64;
    int tx = tid & 15, ty = tid >> 4;
    int row = ty * 4, col = tx * 8;

    // load A tile: 64 x 48 floats = 768 float4
    for (int i = 0; i < 3; i++) {
        int s = tid + i * 256;
        int r = s / 12, c4 = (s % 12) * 4;
        float4 v = *reinterpret_cast<const float4*>(g_xdbl + (size_t)(m0 + r) * XDB + c4);
        As[c4 + 0][r] = v.x; As[c4 + 1][r] = v.y; As[c4 + 2][r] = v.z; As[c4 + 3][r] = v.w;
    }
    // load B tile: 128 x 48 = 1536 float4
    for (int i = 0; i < 6; i++) {
        int s = tid + i * 256;
        int r = s / 12, c4 = (s % 12) * 4;
        float4 v = *reinterpret_cast<const float4*>(Wd + (size_t)(n0 + r) * RK + c4);
        Bs[c4 + 0][r] = v.x; Bs[c4 + 1][r] = v.y; Bs[c4 + 2][r] = v.z; Bs[c4 + 3][r] = v.w;
    }
    __syncthreads();

    float acc[4][8];
#pragma unroll
    for (int i = 0; i < 4; i++)
#pragma unroll
        for (int j = 0; j < 8; j++) acc[i][j] = 0.f;
#pragma unroll
    for (int k = 0; k < 48; k++) {
        float a4[4], b8[8];
#pragma unroll
        for (int i = 0; i < 4; i++) a4[i] = As[k][row + i];
#pragma unroll
        for (int j = 0; j < 8; j++) b8[j] = Bs[k][col + j];
#pragma unroll
        for (int i = 0; i < 4; i++)
#pragma unroll
            for (int j = 0; j < 8; j++)
                acc[i][j] = fmaf(a4[i], b8[j], acc[i][j]);
    }
#pragma unroll
    for (int i = 0; i < 4; i++)
#pragma unroll
        for (int j = 0; j < 8; j++)
            g_dt[(size_t)(m0 + row + i) * DI + n0 + col + j] = acc[i][j];
}

// ================= prep: per (b,t) scalars + pack =================
// Rank-1 Newton-Schulz closed form:
//   G = u k^T  (u = dt_t * x),  N = ||u||*||k||, t1 = 1/(N+1e-7)
//   NS(G) = s * u k^T,  s = a*t1 + b*t1^3*N^2 + c*t1^5*N^4
__global__ __launch_bounds__(256)
void prep_kernel(const float* __restrict__ dt_bias, const float* __restrict__ Dv) {
    int m = blockIdx.x;
    int tid = threadIdx.x;
    __shared__ float s_ksq[16];
    __shared__ float s_kk, s_su;
    __shared__ float red[8];

    if (tid < 48) {
        float v = g_xdbl[(size_t)m * XDB + 32 + tid]; // cols 32..79 => [pad.. no]
        // careful: k at col 48, q at 64 -> handled below instead
    }
    // k / ksq / q into g_knq
    if (tid < 16) {
        float kv = g_xdbl[(size_t)m * XDB + 48 + tid];
        s_ksq[tid] = kv * kv;
        g_knq[(size_t)m * 48 + tid] = kv;
        g_knq[(size_t)m * 48 + 16 + tid] = kv * kv;
        g_knq[(size_t)m * 48 + 32 + tid] = g_xdbl[(size_t)m * XDB + 64 + tid];
    }
    __syncthreads();
    if (tid == 0) {
        float kk = 0.f;
#pragma unroll
        for (int n = 0; n < 16; n++) kk += s_ksq[n];
        s_kk = kk;
    }
    __syncthreads();
    float kk = s_kk;

    float u[6], dtt[6], xv[6];
    float su = 0.f;
#pragma unroll
    for (int i = 0; i < 6; i++) {
        int d = tid + i * 256;
        float dtr = g_dt[(size_t)m * DI + d] + dt_bias[d];
        float s0 = 1.f / (1.f + __expf(-dtr));
        float dv = s0 / (1.f + s0 * kk);
        float x = g_xact[(size_t)m * DI + d];
        float uu = dv * x;
        su += uu * uu;
        u[i] = uu; dtt[i] = dv; xv[i] = x;
    }
    // block reduce su
#pragma unroll
    for (int off = 16; off > 0; off >>= 1) su += __shfl_xor_sync(0xffffffffu, su, off);
    if ((tid & 31) == 0) red[tid >> 5] = su;
    __syncthreads();
    if (tid == 0) {
        float s = 0.f;
#pragma unroll
        for (int i = 0; i < 8; i++) s += red[i];
        s_su = s;
    }
    __syncthreads();

    float Nn = sqrtf(s_su * kk);
    float t1 = 1.f / (Nn + 1e-7f);
    float nt = Nn * t1;
    float nt2 = nt * nt;
    float s = t1 * (3.4445f + nt2 * (-4.7750f + 2.0315f * nt2));

#pragma unroll
    for (int i = 0; i < 6; i++) {
        int d = tid + i * 256;
        float z = g_xz[(size_t)m * DI2 + DI + d];
        float zs = z / (1.f + __expf(-z));
        g_pack[(size_t)m * DI + d] = make_float4(s * u[i], dtt[i], Dv[d] * xv[i], zs);
    }
}

// ================= sequential scan, fully elementwise per channel =================
// thread = one (b, d). State h[16], v[16] in registers.
//   v[n] = 0.9*v[n] + W*k[n];  h[n] = (1 - dtt*k2[n])*h[n] + v[n];
//   y = D*x + sum_n h[n]*q[n];  out = y * silu(z)
__global__ __launch_bounds__(128)
void scan_kernel() {
    int d = blockIdx.x * 128 + threadIdx.x;
    int b = blockIdx.y;
    int tid = threadIdx.x;
    __shared__ float kn[8][48];

    float v[DS], h[DS];
#pragma unroll
    for (int n = 0; n < DS; n++) { v[n] = 0.f; h[n] = 0.f; }

    for (int w = 0; w < Lz / 8; w++) {
        __syncthreads();
        if (tid < 96) {
            const float4* src = reinterpret_cast<const float4*>(g_knq) +
                                (size_t)(b * Lz + w * 8) * 12 + tid;
            reinterpret_cast<float4*>(&kn[0][0])[tid] = *src;
        }
        __syncthreads();
#pragma unroll
        for (int s = 0; s < 8; s++) {
            size_t m = (size_t)b * Lz + w * 8 + s;
            float4 p = g_pack[m * DI + d];
            float kv[48];
#pragma unroll
            for (int i = 0; i < 12; i++)
                reinterpret_cast<float4*>(kv)[i] = reinterpret_cast<const float4*>(&kn[s][0])[i];
            float y = p.z;
#pragma unroll
            for (int n = 0; n < DS; n++) {
                float wv = p.x * kv[n];
                v[n] = fmaf(0.9f, v[n], wv);
                float dA = fmaf(-p.y, kv[16 + n], 1.0f);
                h[n] = fmaf(dA, h[n], v[n]);
                y = fmaf(h[n], kv[32 + n], y);
            }
            g_yg[m * DI + d] = y * p.w;
        }
    }
}

// ================= launch =================
extern "C" void kernel_launch(void* const* d_in, const int* in_sizes, int n_in,
                              void* d_out, int out_size) {
    const float* hs        = (const float*)d_in[0];
    const float* in_proj_w = (const float*)d_in[1];
    const float* conv_w    = (const float*)d_in[2];
    const float* conv_b    = (const float*)d_in[3];
    const float* x_proj_w  = (const float*)d_in[4];
    const float* dt_head_w = (const float*)d_in[5];
    const float* dt_head_b = (const float*)d_in[6];
    const float* out_proj  = (const float*)d_in[7];
    const float* Dv        = (const float*)d_in[8];
    float* out = (float*)d_out;

    void *p_xz, *p_yg;
    cudaGetSymbolAddress(&p_xz, g_xz);
    cudaGetSymbolAddress(&p_yg, g_yg);

    // 1) xz = hs @ in_proj^T   (2048 x 3072, K=768)
    sgemm128<<<dim3(DI2 / 128, Mz / 128), 256>>>(hs, in_proj_w, (float*)p_xz, Mz, DI2, DM);
    // 2) depthwise conv + SiLU
    conv_silu_kernel<<<dim3(DI / 128, Lz / 64, Bz), 128>>>(conv_w, conv_b);
    // 3) x_dbl = xact @ x_proj^T  (2048 x 80, K=1536)
    xdbl_kernel<<<Mz / 32, 256>>>(x_proj_w);
    // 4) dt = dt_low @ dt_head^T  (2048 x 1536, K=48)
    dt_kernel<<<dim3(DI / 128, Mz / 64), 256>>>(dt_head_w);
    // 5) per-(b,t) Newton-Schulz scalar + pack
    prep_kernel<<<Mz, 256>>>(dt_head_b, Dv);
    // 6) sequential scan
    scan_kernel<<<dim3(DI / 128, Bz), 128>>>();
    // 7) out = yg @ out_proj^T  (2048 x 768, K=1536)
    sgemm128<<<dim3(DM / 128, Mz / 128), 256>>>((const float*)p_yg, out_proj, out, Mz, DM, DI);
}

// round 2
// speedup vs baseline: 1.6137x; 1.6137x over previous
#include <cuda_runtime.h>
#include <cstdint>

#define Bz 2
#define Lz 1024
#define Mz (Bz*Lz)      // 2048
#define DM 768
#define DI 1536
#define DI2 3072
#define DS 16
#define RK 48
#define XDB 80
#define LDP 36          // padded smem row (32 data + 4 pad) -> conflict-free ldmatrix

// ---------------- scratch (no cudaMalloc allowed) ----------------
__device__ __align__(16) float g_xz[Mz*DI2];     // in-proj output: x | z
__device__ __align__(16) float g_xact[Mz*DI];    // conv+silu(x)
__device__ __align__(16) float g_xdbl[Mz*XDB];   // dt_low | k | q
__device__ __align__(16) float g_dt[Mz*DI];      // dt head output
__device__ float4 g_pack[Mz*DI];                 // (W, dtt, D*x, silu(z))
__device__ __align__(16) float g_knq[Mz*48];     // k[16], k^2[16], q[16] per (b,t)
__device__ __align__(16) float g_yg[Mz*DI];      // gated scan output

// ---------------- helpers ----------------
__device__ __forceinline__ uint32_t f2tf32(float x) {
    uint32_t r;
    asm("cvt.rna.tf32.f32 %0, %1;" : "=r"(r) : "f"(x));
    return r;
}

__device__ __forceinline__ void ldsm4(uint32_t& r0, uint32_t& r1, uint32_t& r2, uint32_t& r3,
                                      uint32_t saddr) {
    asm volatile("ldmatrix.sync.aligned.m8n8.x4.shared.b16 {%0,%1,%2,%3}, [%4];"
                 : "=r"(r0), "=r"(r1), "=r"(r2), "=r"(r3) : "r"(saddr));
}

__device__ __forceinline__ void mma_tf32(float* c, uint32_t a0, uint32_t a1, uint32_t a2,
                                         uint32_t a3, uint32_t b0, uint32_t b1) {
    asm volatile(
        "mma.sync.aligned.m16n8k8.row.col.f32.tf32.tf32.f32 "
        "{%0,%1,%2,%3}, {%4,%5,%6,%7}, {%8,%9}, {%0,%1,%2,%3};"
        : "+f"(c[0]), "+f"(c[1]), "+f"(c[2]), "+f"(c[3])
        : "r"(a0), "r"(a1), "r"(a2), "r"(a3), "r"(b0), "r"(b1));
}

// ================= tf32 tensor-core GEMM: C[M,N] = A[M,K] * B[N,K]^T =================
// 128x128 tile, BK=32, 256 threads (8 warps as 2x4), warp tile 64x32.
// K must be a multiple of 16. N arbitrary (guards on B load + C store).
__global__ __launch_bounds__(256, 2)
void mma_gemm(const float* __restrict__ A, const float* __restrict__ B,
              float* __restrict__ C, int M, int N, int K,
              int lda, int ldb, int ldc) {
    __shared__ uint32_t As[128 * LDP];
    __shared__ uint32_t Bs[128 * LDP];
    int tid = threadIdx.x;
    int row0 = blockIdx.y << 7, col0 = blockIdx.x << 7;
    int wid = tid >> 5, lane = tid & 31;
    int wm = (wid >> 2) << 6;          // 0 or 64
    int wn = (wid & 3) << 5;           // 0,32,64,96
    int lr = lane & 7, g = lane >> 3;

    uint32_t sA = (uint32_t)__cvta_generic_to_shared(As);
    uint32_t sB = (uint32_t)__cvta_generic_to_shared(Bs);
    // A frag addr: row = wm + mt*16 + lr + (g&1)*8 ; col = kk*8 + (g>>1)*4
    uint32_t aBase = sA + (uint32_t)(((wm + lr + ((g & 1) << 3)) * LDP + ((g >> 1) << 2)) << 2);
    // B frag addr: row = wn + nt2*16 + lr + (g>>1)*8 ; col = kk*8 + (g&1)*4
    uint32_t bBase = sB + (uint32_t)(((wn + lr + ((g >> 1) << 3)) * LDP + ((g & 1) << 2)) << 2);

    float acc[4][4][4];
#pragma unroll
    for (int i = 0; i < 4; i++)
#pragma unroll
        for (int j = 0; j < 4; j++)
#pragma unroll
            for (int r = 0; r < 4; r++) acc[i][j][r] = 0.f;

    for (int k0 = 0; k0 < K; k0 += 32) {
        // fill smem tiles (with tf32 convert); zero-pad OOB
#pragma unroll
        for (int i = 0; i < 4; i++) {
            int idx = tid + (i << 8);
            int r = idx >> 3;
            int c4 = (idx & 7) << 2;
            bool kok = (k0 + c4) < K;
            float4 av = make_float4(0.f, 0.f, 0.f, 0.f);
            if (kok) av = *reinterpret_cast<const float4*>(A + (size_t)(row0 + r) * lda + k0 + c4);
            uint32_t* da = &As[r * LDP + c4];
            da[0] = f2tf32(av.x); da[1] = f2tf32(av.y); da[2] = f2tf32(av.z); da[3] = f2tf32(av.w);
            float4 bv = make_float4(0.f, 0.f, 0.f, 0.f);
            int brow = col0 + r;
            if (kok && brow < N)
                bv = *reinterpret_cast<const float4*>(B + (size_t)brow * ldb + k0 + c4);
            uint32_t* db = &Bs[r * LDP + c4];
            db[0] = f2tf32(bv.x); db[1] = f2tf32(bv.y); db[2] = f2tf32(bv.z); db[3] = f2tf32(bv.w);
        }
        __syncthreads();
        int nkk = (K - k0) >= 32 ? 4 : ((K - k0) >> 3);
        for (int kk = 0; kk < nkk; kk++) {
            uint32_t a[4][4], bf[2][4];
#pragma unroll
            for (int mt = 0; mt < 4; mt++)
                ldsm4(a[mt][0], a[mt][1], a[mt][2], a[mt][3],
                      aBase + (uint32_t)((((mt << 4) * LDP) + (kk << 3)) << 2));
#pragma unroll
            for (int nt2 = 0; nt2 < 2; nt2++)
                ldsm4(bf[nt2][0], bf[nt2][1], bf[nt2][2], bf[nt2][3],
                      bBase + (uint32_t)((((nt2 << 4) * LDP) + (kk << 3)) << 2));
#pragma unroll
            for (int mt = 0; mt < 4; mt++)
#pragma unroll
                for (int nt = 0; nt < 4; nt++) {
                    uint32_t b0 = bf[nt >> 1][(nt & 1) << 1];
                    uint32_t b1 = bf[nt >> 1][((nt & 1) << 1) + 1];
                    mma_tf32(acc[mt][nt], a[mt][0], a[mt][1], a[mt][2], a[mt][3], b0, b1);
                }
        }
        __syncthreads();
    }
    // epilogue: c0,c1 -> (row, col..col+1); c2,c3 -> (row+8, col..col+1)
    int cr = lane >> 2, cc = (lane & 3) << 1;
#pragma unroll
    for (int mt = 0; mt < 4; mt++)
#pragma unroll
        for (int nt = 0; nt < 4; nt++) {
            int row = row0 + wm + (mt << 4) + cr;
            int col = col0 + wn + (nt << 3) + cc;
            if (col < N) {
                *reinterpret_cast<float2*>(C + (size_t)row * ldc + col) =
                    make_float2(acc[mt][nt][0], acc[mt][nt][1]);
                *reinterpret_cast<float2*>(C + (size_t)(row + 8) * ldc + col) =
                    make_float2(acc[mt][nt][2], acc[mt][nt][3]);
            }
        }
}

// ================= depthwise causal conv (k=4) + SiLU =================
__global__ void conv_silu_kernel(const float* __restrict__ conv_w,
                                 const float* __restrict__ conv_b) {
    int d = blockIdx.x * 128 + threadIdx.x;
    int tc = blockIdx.y;
    int b = blockIdx.z;
    float w0 = conv_w[d * 4 + 0], w1 = conv_w[d * 4 + 1];
    float w2 = conv_w[d * 4 + 2], w3 = conv_w[d * 4 + 3];
    float bias = conv_b[d];
    int t0 = tc * 64;
    size_t base = (size_t)b * Lz;
    float xm3 = (t0 >= 3) ? g_xz[(base + t0 - 3) * DI2 + d] : 0.f;
    float xm2 = (t0 >= 2) ? g_xz[(base + t0 - 2) * DI2 + d] : 0.f;
    float xm1 = (t0 >= 1) ? g_xz[(base + t0 - 1) * DI2 + d] : 0.f;
    for (int t = t0; t < t0 + 64; t++) {
        float xc = g_xz[(base + t) * DI2 + d];
        float a = w0 * xm3 + w1 * xm2 + w2 * xm1 + w3 * xc + bias;
        float s = a / (1.f + __expf(-a));
        g_xact[(base + t) * DI + d] = s;
        xm3 = xm2; xm2 = xm1; xm1 = xc;
    }
}

// ================= prep: rank-1 Newton-Schulz closed form + pack =================
__global__ __launch_bounds__(256)
void prep_kernel(const float* __restrict__ dt_bias, const float* __restrict__ Dv) {
    int m = blockIdx.x;
    int tid = threadIdx.x;
    __shared__ float s_ksq[16];
    __shared__ float s_kk, s_su;
    __shared__ float red[8];

    if (tid < 16) {
        float kv = g_xdbl[(size_t)m * XDB + 48 + tid];
        s_ksq[tid] = kv * kv;
        g_knq[(size_t)m * 48 + tid] = kv;
        g_knq[(size_t)m * 48 + 16 + tid] = kv * kv;
        g_knq[(size_t)m * 48 + 32 + tid] = g_xdbl[(size_t)m * XDB + 64 + tid];
    }
    __syncthreads();
    if (tid == 0) {
        float kk = 0.f;
#pragma unroll
        for (int n = 0; n < 16; n++) kk += s_ksq[n];
        s_kk = kk;
    }
    __syncthreads();
    float kk = s_kk;

    float u[6], dtt[6], xv[6];
    float su = 0.f;
#pragma unroll
    for (int i = 0; i < 6; i++) {
        int d = tid + i * 256;
        float dtr = g_dt[(size_t)m * DI + d] + dt_bias[d];
        float s0 = 1.f / (1.f + __expf(-dtr));
        float dv = s0 / (1.f + s0 * kk);
        float x = g_xact[(size_t)m * DI + d];
        float uu = dv * x;
        su += uu * uu;
        u[i] = uu; dtt[i] = dv; xv[i] = x;
    }
#pragma unroll
    for (int off = 16; off > 0; off >>= 1) su += __shfl_xor_sync(0xffffffffu, su, off);
    if ((tid & 31) == 0) red[tid >> 5] = su;
    __syncthreads();
    if (tid == 0) {
        float s = 0.f;
#pragma unroll
        for (int i = 0; i < 8; i++) s += red[i];
        s_su = s;
    }
    __syncthreads();

    float Nn = sqrtf(s_su * kk);
    float t1 = 1.f / (Nn + 1e-7f);
    float nt = Nn * t1;
    float nt2 = nt * nt;
    float s = t1 * (3.4445f + nt2 * (-4.7750f + 2.0315f * nt2));

#pragma unroll
    for (int i = 0; i < 6; i++) {
        int d = tid + i * 256;
        float z = g_xz[(size_t)m * DI2 + DI + d];
        float zs = z / (1.f + __expf(-z));
        g_pack[(size_t)m * DI + d] = make_float4(s * u[i], dtt[i], Dv[d] * xv[i], zs);
    }
}

// ================= scan: 4-way n-split, thread = (b, d, n-group) =================
// 192 blocks x 64 thr. Each thread owns 4 of 16 states; y reduced over 4 lanes.
__global__ __launch_bounds__(64)
void scan_kernel() {
    int tid = threadIdx.x;
    int ng = tid & 3;
    int d = (blockIdx.x << 4) + (tid >> 2);
    int b = blockIdx.y;
    __shared__ float kn[8 * 48];

    float v0 = 0.f, v1 = 0.f, v2 = 0.f, v3 = 0.f;
    float h0 = 0.f, h1 = 0.f, h2 = 0.f, h3 = 0.f;
    const float4* knq4 = reinterpret_cast<const float4*>(g_knq);

    for (int w = 0; w < Lz / 8; w++) {
        __syncthreads();
#pragma unroll
        for (int i = 0; i < 2; i++) {
            int s = tid + (i << 6);
            if (s < 96)
                reinterpret_cast<float4*>(kn)[s] = knq4[(size_t)(b * Lz + (w << 3)) * 12 + s];
        }
        __syncthreads();
#pragma unroll
        for (int s = 0; s < 8; s++) {
            size_t m = (size_t)b * Lz + (w << 3) + s;
            float4 p = g_pack[m * DI + d];
            const float* kb = kn + s * 48 + (ng << 2);
            float4 kv = *reinterpret_cast<const float4*>(kb);
            float4 k2 = *reinterpret_cast<const float4*>(kb + 16);
            float4 qv = *reinterpret_cast<const float4*>(kb + 32);
            v0 = fmaf(0.9f, v0, p.x * kv.x); h0 = fmaf(fmaf(-p.y, k2.x, 1.f), h0, v0);
            v1 = fmaf(0.9f, v1, p.x * kv.y); h1 = fmaf(fmaf(-p.y, k2.y, 1.f), h1, v1);
            v2 = fmaf(0.9f, v2, p.x * kv.z); h2 = fmaf(fmaf(-p.y, k2.z, 1.f), h2, v2);
            v3 = fmaf(0.9f, v3, p.x * kv.w); h3 = fmaf(fmaf(-p.y, k2.w, 1.f), h3, v3);
            float y = fmaf(h0, qv.x, fmaf(h1, qv.y, fmaf(h2, qv.z, h3 * qv.w)));
            y += __shfl_xor_sync(0xffffffffu, y, 1);
            y += __shfl_xor_sync(0xffffffffu, y, 2);
            if (ng == 0) g_yg[m * DI + d] = (y + p.z) * p.w;
        }
    }
}

// ================= launch =================
extern "C" void kernel_launch(void* const* d_in, const int* in_sizes, int n_in,
                              void* d_out, int out_size) {
    const float* hs        = (const float*)d_in[0];
    const float* in_proj_w = (const float*)d_in[1];
    const float* conv_w    = (const float*)d_in[2];
    const float* conv_b    = (const float*)d_in[3];
    const float* x_proj_w  = (const float*)d_in[4];
    const float* dt_head_w = (const float*)d_in[5];
    const float* dt_head_b = (const float*)d_in[6];
    const float* out_proj  = (const float*)d_in[7];
    const float* Dv        = (const float*)d_in[8];
    float* out = (float*)d_out;

    void *p_xz, *p_xact, *p_xdbl, *p_dt, *p_yg;
    cudaGetSymbolAddress(&p_xz, g_xz);
    cudaGetSymbolAddress(&p_xact, g_xact);
    cudaGetSymbolAddress(&p_xdbl, g_xdbl);
    cudaGetSymbolAddress(&p_dt, g_dt);
    cudaGetSymbolAddress(&p_yg, g_yg);

    // 1) xz = hs @ in_proj^T   (2048 x 3072, K=768)
    mma_gemm<<<dim3(DI2 / 128, Mz / 128), 256>>>(hs, in_proj_w, (float*)p_xz,
                                                 Mz, DI2, DM, DM, DM, DI2);
    // 2) depthwise conv + SiLU
    conv_silu_kernel<<<dim3(DI / 128, Lz / 64, Bz), 128>>>(conv_w, conv_b);
    // 3) x_dbl = xact @ x_proj^T  (2048 x 80, K=1536)
    mma_gemm<<<dim3(1, Mz / 128), 256>>>((const float*)p_xact, x_proj_w, (float*)p_xdbl,
                                         Mz, XDB, DI, DI, DI, XDB);
    // 4) dt = dt_low @ dt_head^T  (2048 x 1536, K=48, A strided in g_xdbl)
    mma_gemm<<<dim3(DI / 128, Mz / 128), 256>>>((const float*)p_xdbl, dt_head_w, (float*)p_dt,
                                                Mz, DI, RK, XDB, RK, DI);
    // 5) per-(b,t) Newton-Schulz scalar + pack
    prep_kernel<<<Mz, 256>>>(dt_head_b, Dv);
    // 6) scan (4-way n-split)
    scan_kernel<<<dim3(DI / 16, Bz), 64>>>();
    // 7) out = yg @ out_proj^T  (2048 x 768, K=1536)
    mma_gemm<<<dim3(DM / 128, Mz / 128), 256>>>((const float*)p_yg, out_proj, out,
                                                Mz, DM, DI, DI, DI, DM);
}